// round 4
// baseline (speedup 1.0000x reference)
#include <cuda_runtime.h>
#include <math.h>

// Problem dims
#define NTOK 32768
#define ADIM 6
#define HDIM 1024
#define DDIM 128
#define KCB  4096

#define VQ_BLOCKS (NTOK / 128)   // 256

// Output layout (float32, concatenated in reference-return order)
#define OUT_INDS 0
#define OUT_Q    (NTOK)
#define OUT_REC  (NTOK + NTOK * DDIM)
#define OUT_LOSS (NTOK + NTOK * DDIM + NTOK * ADIM)

typedef unsigned long long u64;

// packed f32x2 FMA: two independent IEEE fp32 FMAs per instruction (bit-exact
// per lane vs FFMA; Blackwell-only, ptxas never auto-generates it)
__device__ __forceinline__ u64 fma2(u64 a, u64 b, u64 c)
{
    u64 d;
    asm("fma.rn.f32x2 %0, %1, %2, %3;" : "=l"(d) : "l"(a), "l"(b), "l"(c));
    return d;
}
__device__ __forceinline__ float2 u64_as_f2(u64 v)
{
    float2 r;
    asm("mov.b64 {%0, %1}, %2;" : "=f"(r.x), "=f"(r.y) : "l"(v));
    return r;
}

// -------- scratch (device globals; no runtime allocation) --------
__device__ float g_h1[NTOK * HDIM];
__device__ float g_h2[NTOK * HDIM];
__device__ float g_lat[NTOK * DDIM];
__device__ float g_q[NTOK * DDIM];
__device__ float g_ln[NTOK];
__device__ float g_cn[KCB];
__device__ float g_part[VQ_BLOCKS];

// ---------------------------------------------------------------------------
// XLA-style row sum-of-squares (order-critical for argmin tie replication)
// ---------------------------------------------------------------------------
__device__ __forceinline__ float row_sumsq_128(const float* __restrict__ row, int lane)
{
    float acc = 0.f;
#pragma unroll
    for (int i = 0; i < 4; i++) {
        float v = row[lane + i * 32];
        acc = __fadd_rn(acc, __fmul_rn(v, v));
    }
#pragma unroll
    for (int off = 16; off >= 1; off >>= 1)
        acc = __fadd_rn(acc, __shfl_down_sync(0xffffffffu, acc, off));
    return acc;
}

__global__ void k_cnorm(const float* __restrict__ cb, float* __restrict__ cn)
{
    int w = (blockIdx.x * blockDim.x + threadIdx.x) >> 5;
    int lane = threadIdx.x & 31;
    float s = row_sumsq_128(cb + w * DDIM, lane);
    if (lane == 0) cn[w] = s;
}

__global__ void k_rownorm(const float* __restrict__ lat, float* __restrict__ ln)
{
    int w = (blockIdx.x * blockDim.x + threadIdx.x) >> 5;
    int lane = threadIdx.x & 31;
    float s = row_sumsq_128(lat + w * DDIM, lane);
    if (lane == 0) ln[w] = s;
}

// ---------------------------------------------------------------------------
// Encoder layer 1 (A=6, elementwise-ish)
// ---------------------------------------------------------------------------
__global__ void k_enc1(const float* __restrict__ act, const float* __restrict__ W1,
                       const float* __restrict__ b1, float* __restrict__ h1)
{
    int gid = blockIdx.x * blockDim.x + threadIdx.x;
    int n = gid >> 10;
    int h = gid & 1023;
    const float* a = act + n * ADIM;
    float s = 0.f;
    s = __fmaf_rn(a[0], W1[0 * HDIM + h], s);
    s = __fmaf_rn(a[1], W1[1 * HDIM + h], s);
    s = __fmaf_rn(a[2], W1[2 * HDIM + h], s);
    s = __fmaf_rn(a[3], W1[3 * HDIM + h], s);
    s = __fmaf_rn(a[4], W1[4 * HDIM + h], s);
    s = __fmaf_rn(a[5], W1[5 * HDIM + h], s);
    s = __fadd_rn(s, b1[h]);
    h1[gid] = fmaxf(s, 0.f);
}

// ---------------------------------------------------------------------------
// SGEMM: C = act(A[M,K]@B[K,N] + bias). 128x128 tile, BK=16, double-buffered,
// A rows pre-duplicated in smem for fma.f32x2. Per-(i,j) accumulation chain is
// a single FFMA chain over k ascending (identical math to previous pass).
// ---------------------------------------------------------------------------
template <int RELU>
__global__ __launch_bounds__(256)
void sgemm(const float* __restrict__ Am, const float* __restrict__ Bm,
           const float* __restrict__ bias, float* __restrict__ Cm,
           int Nn, int Kk)
{
    __shared__ float As2[2][16][256];   // [buf][k][2*m] duplicated pairs (32KB)
    __shared__ float Bs[2][16][128];    // [buf][k][n] (16KB)

    int tid = threadIdx.x;
    int tx = tid & 15;
    int ty = tid >> 4;
    int mb = blockIdx.y * 128;
    int nb = blockIdx.x * 128;

    int arow = tid >> 1;
    int acol = (tid & 1) * 8;
    int brow = tid >> 5;            // 0..7 (also loads brow+8)
    int bcol = (tid & 31) * 4;

    const float* Ap = Am + (mb + arow) * Kk + acol;
    const float* Bp = Bm + brow * Nn + nb + bcol;

    u64 acc[8][4];
#pragma unroll
    for (int i = 0; i < 8; i++)
#pragma unroll
        for (int j = 0; j < 4; j++) acc[i][j] = 0ull;

    // prologue: tile 0 straight into buffer 0
    {
        float4 a0 = *(const float4*)Ap;
        float4 a1 = *(const float4*)(Ap + 4);
        float4 b0 = *(const float4*)Bp;
        float4 b1 = *(const float4*)(Bp + 8 * Nn);
        Ap += 16; Bp += 16 * Nn;
        *(float2*)&As2[0][acol + 0][2 * arow] = make_float2(a0.x, a0.x);
        *(float2*)&As2[0][acol + 1][2 * arow] = make_float2(a0.y, a0.y);
        *(float2*)&As2[0][acol + 2][2 * arow] = make_float2(a0.z, a0.z);
        *(float2*)&As2[0][acol + 3][2 * arow] = make_float2(a0.w, a0.w);
        *(float2*)&As2[0][acol + 4][2 * arow] = make_float2(a1.x, a1.x);
        *(float2*)&As2[0][acol + 5][2 * arow] = make_float2(a1.y, a1.y);
        *(float2*)&As2[0][acol + 6][2 * arow] = make_float2(a1.z, a1.z);
        *(float2*)&As2[0][acol + 7][2 * arow] = make_float2(a1.w, a1.w);
        *(float4*)&Bs[0][brow][bcol] = b0;
        *(float4*)&Bs[0][brow + 8][bcol] = b1;
    }
    __syncthreads();

    int nt = Kk >> 4;
    for (int t = 0; t < nt; t++) {
        int cur = t & 1;
        float4 a0, a1, b0, b1;
        bool pf = (t + 1 < nt);
        if (pf) {
            a0 = *(const float4*)Ap;
            a1 = *(const float4*)(Ap + 4);
            b0 = *(const float4*)Bp;
            b1 = *(const float4*)(Bp + 8 * Nn);
            Ap += 16; Bp += 16 * Nn;
        }

#pragma unroll
        for (int kk = 0; kk < 16; kk++) {
            const float* ar = &As2[cur][kk][ty * 16];
            ulonglong2 A0 = *(const ulonglong2*)(ar);
            ulonglong2 A1 = *(const ulonglong2*)(ar + 4);
            ulonglong2 A2 = *(const ulonglong2*)(ar + 8);
            ulonglong2 A3 = *(const ulonglong2*)(ar + 12);
            const float* br = &Bs[cur][kk][tx * 8];
            ulonglong2 B0 = *(const ulonglong2*)(br);
            ulonglong2 B1 = *(const ulonglong2*)(br + 4);
            u64 av[8] = {A0.x, A0.y, A1.x, A1.y, A2.x, A2.y, A3.x, A3.y};
            u64 bv[4] = {B0.x, B0.y, B1.x, B1.y};
#pragma unroll
            for (int i = 0; i < 8; i++)
#pragma unroll
                for (int j = 0; j < 4; j++)
                    acc[i][j] = fma2(av[i], bv[j], acc[i][j]);
        }

        if (pf) {
            int nxt = 1 - cur;
            *(float2*)&As2[nxt][acol + 0][2 * arow] = make_float2(a0.x, a0.x);
            *(float2*)&As2[nxt][acol + 1][2 * arow] = make_float2(a0.y, a0.y);
            *(float2*)&As2[nxt][acol + 2][2 * arow] = make_float2(a0.z, a0.z);
            *(float2*)&As2[nxt][acol + 3][2 * arow] = make_float2(a0.w, a0.w);
            *(float2*)&As2[nxt][acol + 4][2 * arow] = make_float2(a1.x, a1.x);
            *(float2*)&As2[nxt][acol + 5][2 * arow] = make_float2(a1.y, a1.y);
            *(float2*)&As2[nxt][acol + 6][2 * arow] = make_float2(a1.z, a1.z);
            *(float2*)&As2[nxt][acol + 7][2 * arow] = make_float2(a1.w, a1.w);
            *(float4*)&Bs[nxt][brow][bcol] = b0;
            *(float4*)&Bs[nxt][brow + 8][bcol] = b1;
        }
        __syncthreads();
    }

#pragma unroll
    for (int i = 0; i < 8; i++) {
        int row = mb + ty * 8 + i;
        float* Crow = Cm + row * Nn + nb + tx * 8;
        const float* bb = bias + nb + tx * 8;
#pragma unroll
        for (int jp = 0; jp < 4; jp++) {
            float2 v = u64_as_f2(acc[i][jp]);
            float v0 = __fadd_rn(v.x, bb[2 * jp]);
            float v1 = __fadd_rn(v.y, bb[2 * jp + 1]);
            if (RELU) { v0 = fmaxf(v0, 0.f); v1 = fmaxf(v1, 0.f); }
            Crow[2 * jp] = v0;
            Crow[2 * jp + 1] = v1;
        }
    }
}

// ---------------------------------------------------------------------------
// VQ: 128 rows/block vs all 4096 codes. Same dist rounding chain + tie-break
// as the passing version; compute core is the pipelined fma2 GEMM.
// Dynamic smem: Ls[128][132] transposed latents + Cs[2][16][256] dup'd codes.
// ---------------------------------------------------------------------------
#define VQ_SMEM_BYTES ((128 * 132 + 2 * 16 * 256) * 4)

__global__ __launch_bounds__(256)
void k_vq(const float* __restrict__ lat, const float* __restrict__ cb,
          const float* __restrict__ cn, const float* __restrict__ ln,
          float* __restrict__ out, float* __restrict__ gq,
          float* __restrict__ part)
{
    extern __shared__ float sm[];
    float (*Ls)[132] = (float(*)[132])sm;        // [d][row]
    float* Cs = sm + 128 * 132;                  // [buf][kk][2*code]
    __shared__ int s_ind[128];
    __shared__ float s_red[256];

    int tid = threadIdx.x;
    int tx = tid & 15;
    int ty = tid >> 4;
    int m0 = blockIdx.x * 128;

    // latents tile transposed
#pragma unroll
    for (int i = 0; i < 16; i++) {
        int e = tid + i * 256;
        int r = e >> 5;
        int d4 = (e & 31) * 4;
        float4 v = *(const float4*)(lat + (m0 + r) * DDIM + d4);
        Ls[d4 + 0][r] = v.x;
        Ls[d4 + 1][r] = v.y;
        Ls[d4 + 2][r] = v.z;
        Ls[d4 + 3][r] = v.w;
    }

    int code_l = tid >> 1;
    int dsub = (tid & 1) * 8;

    // prologue: chunk 0 (tile 0, d0=0) into buffer 0, duplicated pairs
    {
        const float* p = cb + code_l * DDIM + dsub;
        float4 v0 = *(const float4*)p;
        float4 v1 = *(const float4*)(p + 4);
        float* dst = Cs;   // buf 0
        *(float2*)&dst[(dsub + 0) * 256 + 2 * code_l] = make_float2(v0.x, v0.x);
        *(float2*)&dst[(dsub + 1) * 256 + 2 * code_l] = make_float2(v0.y, v0.y);
        *(float2*)&dst[(dsub + 2) * 256 + 2 * code_l] = make_float2(v0.z, v0.z);
        *(float2*)&dst[(dsub + 3) * 256 + 2 * code_l] = make_float2(v0.w, v0.w);
        *(float2*)&dst[(dsub + 4) * 256 + 2 * code_l] = make_float2(v1.x, v1.x);
        *(float2*)&dst[(dsub + 5) * 256 + 2 * code_l] = make_float2(v1.y, v1.y);
        *(float2*)&dst[(dsub + 6) * 256 + 2 * code_l] = make_float2(v1.z, v1.z);
        *(float2*)&dst[(dsub + 7) * 256 + 2 * code_l] = make_float2(v1.w, v1.w);
    }
    __syncthreads();

    float Lrow[8];
#pragma unroll
    for (int i = 0; i < 8; i++) Lrow[i] = ln[m0 + ty * 8 + i];

    float bestv[8];
    int besti[8];
#pragma unroll
    for (int i = 0; i < 8; i++) { bestv[i] = 3.4e38f; besti[i] = 0; }

    u64 acc[8][4];   // [code j][row pair]
#pragma unroll
    for (int j = 0; j < 8; j++)
#pragma unroll
        for (int ip = 0; ip < 4; ip++) acc[j][ip] = 0ull;

    for (int ci = 0; ci < 256; ci++) {            // 32 tiles x 8 d-chunks
        int cur = ci & 1;
        float4 p0, p1;
        bool pf = (ci + 1 < 256);
        if (pf) {
            int nt2 = (ci + 1) >> 3;
            int nd0 = ((ci + 1) & 7) * 16;
            const float* p = cb + (nt2 * 128 + code_l) * DDIM + nd0 + dsub;
            p0 = *(const float4*)p;
            p1 = *(const float4*)(p + 4);
        }

        int d0 = (ci & 7) * 16;
        const float* Cbuf = Cs + cur * 16 * 256;
#pragma unroll
        for (int kk = 0; kk < 16; kk++) {
            const float* lr = &Ls[d0 + kk][ty * 8];
            ulonglong2 L0 = *(const ulonglong2*)(lr);
            ulonglong2 L1 = *(const ulonglong2*)(lr + 4);
            u64 lp[4] = {L0.x, L0.y, L1.x, L1.y};
            const float* cr = Cbuf + kk * 256 + 2 * tx;
#pragma unroll
            for (int j = 0; j < 8; j++) {
                u64 cd = *(const u64*)(cr + 32 * j);
#pragma unroll
                for (int ip = 0; ip < 4; ip++)
                    acc[j][ip] = fma2(cd, lp[ip], acc[j][ip]);
            }
        }

        if ((ci & 7) == 7) {
            int tile = ci >> 3;
#pragma unroll
            for (int j = 0; j < 8; j++) {
                int code = tile * 128 + tx + 16 * j;
                float cnv = __ldg(cn + code);
#pragma unroll
                for (int ip = 0; ip < 4; ip++) {
                    float2 dv = u64_as_f2(acc[j][ip]);
                    int i0 = 2 * ip;
                    float t0 = __fadd_rn(Lrow[i0], cnv);
                    float dist0 = __fsub_rn(t0, __fmul_rn(2.f, dv.x));
                    if (dist0 < bestv[i0]) { bestv[i0] = dist0; besti[i0] = code; }
                    int i1 = 2 * ip + 1;
                    float t1 = __fadd_rn(Lrow[i1], cnv);
                    float dist1 = __fsub_rn(t1, __fmul_rn(2.f, dv.y));
                    if (dist1 < bestv[i1]) { bestv[i1] = dist1; besti[i1] = code; }
                    acc[j][ip] = 0ull;
                }
            }
        }

        if (pf) {
            float* dst = Cs + (1 - cur) * 16 * 256;
            *(float2*)&dst[(dsub + 0) * 256 + 2 * code_l] = make_float2(p0.x, p0.x);
            *(float2*)&dst[(dsub + 1) * 256 + 2 * code_l] = make_float2(p0.y, p0.y);
            *(float2*)&dst[(dsub + 2) * 256 + 2 * code_l] = make_float2(p0.z, p0.z);
            *(float2*)&dst[(dsub + 3) * 256 + 2 * code_l] = make_float2(p0.w, p0.w);
            *(float2*)&dst[(dsub + 4) * 256 + 2 * code_l] = make_float2(p1.x, p1.x);
            *(float2*)&dst[(dsub + 5) * 256 + 2 * code_l] = make_float2(p1.y, p1.y);
            *(float2*)&dst[(dsub + 6) * 256 + 2 * code_l] = make_float2(p1.z, p1.z);
            *(float2*)&dst[(dsub + 7) * 256 + 2 * code_l] = make_float2(p1.w, p1.w);
        }
        __syncthreads();
    }

    // per-row argmin reduce over the 16 tx lanes (lower index wins ties)
#pragma unroll
    for (int i = 0; i < 8; i++) {
        float v = bestv[i];
        int ix = besti[i];
#pragma unroll
        for (int off = 8; off >= 1; off >>= 1) {
            float ov = __shfl_down_sync(0xffffffffu, v, off, 16);
            int oi = __shfl_down_sync(0xffffffffu, ix, off, 16);
            if (ov < v || (ov == v && oi < ix)) { v = ov; ix = oi; }
        }
        if (tx == 0) {
            int mloc = ty * 8 + i;
            s_ind[mloc] = ix;
            out[OUT_INDS + m0 + mloc] = (float)ix;
        }
    }
    __syncthreads();

    // gather quantized, straight-through, loss partial
    float lsum = 0.f;
#pragma unroll 4
    for (int e = tid; e < 128 * DDIM; e += 256) {
        int r = e >> 7;
        int d = e & 127;
        float l = Ls[d][r];
        float q = cb[s_ind[r] * DDIM + d];
        float qmL = q - l;
        float qst = l + qmL;
        int m = m0 + r;
        out[OUT_Q + m * DDIM + d] = qst;
        gq[m * DDIM + d] = qst;
        lsum += qmL * qmL;
    }
    s_red[tid] = lsum;
    __syncthreads();
    for (int s = 128; s > 0; s >>= 1) {
        if (tid < s) s_red[tid] += s_red[tid + s];
        __syncthreads();
    }
    if (tid == 0) part[blockIdx.x] = s_red[0];
}

// ---------------------------------------------------------------------------
// Decoder layer 3: recons = tanh(d2 @ Wd3 + bd3). Warp per row.
// ---------------------------------------------------------------------------
__global__ void k_dec3(const float* __restrict__ d2, const float* __restrict__ Wd3,
                       const float* __restrict__ bd3, float* __restrict__ out)
{
    int warp = (blockIdx.x * blockDim.x + threadIdx.x) >> 5;
    int lane = threadIdx.x & 31;
    const float* row = d2 + warp * HDIM;
    float a0 = 0.f, a1 = 0.f, a2 = 0.f, a3 = 0.f, a4 = 0.f, a5 = 0.f;
#pragma unroll 4
    for (int k = lane; k < HDIM; k += 32) {
        float v = row[k];
        const float* w = Wd3 + k * ADIM;
        a0 += v * w[0]; a1 += v * w[1]; a2 += v * w[2];
        a3 += v * w[3]; a4 += v * w[4]; a5 += v * w[5];
    }
#pragma unroll
    for (int off = 16; off; off >>= 1) {
        a0 += __shfl_xor_sync(0xffffffffu, a0, off);
        a1 += __shfl_xor_sync(0xffffffffu, a1, off);
        a2 += __shfl_xor_sync(0xffffffffu, a2, off);
        a3 += __shfl_xor_sync(0xffffffffu, a3, off);
        a4 += __shfl_xor_sync(0xffffffffu, a4, off);
        a5 += __shfl_xor_sync(0xffffffffu, a5, off);
    }
    if (lane == 0) {
        float* o = out + OUT_REC + warp * ADIM;
        o[0] = tanhf(a0 + bd3[0]);
        o[1] = tanhf(a1 + bd3[1]);
        o[2] = tanhf(a2 + bd3[2]);
        o[3] = tanhf(a3 + bd3[3]);
        o[4] = tanhf(a4 + bd3[4]);
        o[5] = tanhf(a5 + bd3[5]);
    }
}

// ---------------------------------------------------------------------------
// Final loss reduction
// ---------------------------------------------------------------------------
__global__ void k_loss(const float* __restrict__ part, float* __restrict__ out)
{
    __shared__ float s[256];
    int tid = threadIdx.x;
    s[tid] = part[tid];
    __syncthreads();
    for (int st = 128; st > 0; st >>= 1) {
        if (tid < st) s[tid] += s[tid + st];
        __syncthreads();
    }
    if (tid == 0)
        out[OUT_LOSS] = 1.25f * s[0] / (float)(NTOK * DDIM);
}

// ---------------------------------------------------------------------------
extern "C" void kernel_launch(void* const* d_in, const int* in_sizes, int n_in,
                              void* d_out, int out_size)
{
    const float* action = (const float*)d_in[0];
    const float* W1   = (const float*)d_in[1];
    const float* b1   = (const float*)d_in[2];
    const float* W2   = (const float*)d_in[3];
    const float* b2   = (const float*)d_in[4];
    const float* Wmu  = (const float*)d_in[5];
    const float* bmu  = (const float*)d_in[6];
    const float* cb   = (const float*)d_in[7];
    const float* Wd1  = (const float*)d_in[8];
    const float* bd1  = (const float*)d_in[9];
    const float* Wd2  = (const float*)d_in[10];
    const float* bd2  = (const float*)d_in[11];
    const float* Wd3  = (const float*)d_in[12];
    const float* bd3  = (const float*)d_in[13];
    float* out = (float*)d_out;

    float *p_h1, *p_h2, *p_lat, *p_q, *p_ln, *p_cn, *p_part;
    cudaGetSymbolAddress((void**)&p_h1, g_h1);
    cudaGetSymbolAddress((void**)&p_h2, g_h2);
    cudaGetSymbolAddress((void**)&p_lat, g_lat);
    cudaGetSymbolAddress((void**)&p_q, g_q);
    cudaGetSymbolAddress((void**)&p_ln, g_ln);
    cudaGetSymbolAddress((void**)&p_cn, g_cn);
    cudaGetSymbolAddress((void**)&p_part, g_part);

    cudaFuncSetAttribute(k_vq, cudaFuncAttributeMaxDynamicSharedMemorySize,
                         VQ_SMEM_BYTES);

    // codebook norms
    k_cnorm<<<KCB / 8, 256>>>(cb, p_cn);
    // encoder
    k_enc1<<<(NTOK * HDIM) / 256, 256>>>(action, W1, b1, p_h1);
    sgemm<1><<<dim3(HDIM / 128, NTOK / 128), 256>>>(p_h1, W2, b2, p_h2, HDIM, HDIM);
    sgemm<0><<<dim3(DDIM / 128, NTOK / 128), 256>>>(p_h2, Wmu, bmu, p_lat, DDIM, HDIM);
    // row norms of latents (XLA-order reduction)
    k_rownorm<<<NTOK / 8, 256>>>(p_lat, p_ln);
    // vector quantization
    k_vq<<<VQ_BLOCKS, 256, VQ_SMEM_BYTES>>>(p_lat, cb, p_cn, p_ln, out, p_q, p_part);
    // decoder
    sgemm<1><<<dim3(HDIM / 128, NTOK / 128), 256>>>(p_q, Wd1, bd1, p_h1, HDIM, DDIM);
    sgemm<1><<<dim3(HDIM / 128, NTOK / 128), 256>>>(p_h1, Wd2, bd2, p_h2, HDIM, HDIM);
    k_dec3<<<NTOK / 8, 256>>>(p_h2, Wd3, bd3, out);
    // scalar loss
    k_loss<<<1, 256>>>(p_part, out);
}

// round 6
// speedup vs baseline: 1.3426x; 1.3426x over previous
#include <cuda_runtime.h>
#include <math.h>
#include <stdint.h>

// Problem dims
#define NTOK 32768
#define ADIM 6
#define HDIM 1024
#define DDIM 128
#define KCB  4096

#define VQ_BLOCKS (NTOK / 64)   // 512

// Output layout (float32, concatenated in reference-return order)
#define OUT_INDS 0
#define OUT_Q    (NTOK)
#define OUT_REC  (NTOK + NTOK * DDIM)
#define OUT_LOSS (NTOK + NTOK * DDIM + NTOK * ADIM)

// -------- scratch (device globals; no runtime allocation) --------
__device__ float g_h1[NTOK * HDIM];
__device__ float g_h2[NTOK * HDIM];
__device__ float g_lat[NTOK * DDIM];
__device__ float g_q[NTOK * DDIM];
__device__ float g_ln[NTOK];
__device__ float g_cn[KCB];
__device__ float g_part[VQ_BLOCKS];
__device__ float g_wt1[HDIM * DDIM];   // Wd1^T  [1024][128]
__device__ float g_wt2[HDIM * HDIM];   // Wd2^T  [1024][1024]

// ---------------------------------------------------------------------------
// XLA-style row sum-of-squares (order-critical for argmin tie replication)
// ---------------------------------------------------------------------------
__device__ __forceinline__ float row_sumsq_128(const float* __restrict__ row, int lane)
{
    float acc = 0.f;
#pragma unroll
    for (int i = 0; i < 4; i++) {
        float v = row[lane + i * 32];
        acc = __fadd_rn(acc, __fmul_rn(v, v));
    }
#pragma unroll
    for (int off = 16; off >= 1; off >>= 1)
        acc = __fadd_rn(acc, __shfl_down_sync(0xffffffffu, acc, off));
    return acc;
}

__global__ void k_cnorm(const float* __restrict__ cb, float* __restrict__ cn)
{
    int w = (blockIdx.x * blockDim.x + threadIdx.x) >> 5;
    int lane = threadIdx.x & 31;
    float s = row_sumsq_128(cb + w * DDIM, lane);
    if (lane == 0) cn[w] = s;
}

__global__ void k_rownorm(const float* __restrict__ lat, float* __restrict__ ln)
{
    int w = (blockIdx.x * blockDim.x + threadIdx.x) >> 5;
    int lane = threadIdx.x & 31;
    float s = row_sumsq_128(lat + w * DDIM, lane);
    if (lane == 0) ln[w] = s;
}

// ---------------------------------------------------------------------------
// Encoder layer 1 (A=6)
// ---------------------------------------------------------------------------
__global__ void k_enc1(const float* __restrict__ act, const float* __restrict__ W1,
                       const float* __restrict__ b1, float* __restrict__ h1)
{
    int gid = blockIdx.x * blockDim.x + threadIdx.x;
    int n = gid >> 10;
    int h = gid & 1023;
    const float* a = act + n * ADIM;
    float s = 0.f;
    s = __fmaf_rn(a[0], W1[0 * HDIM + h], s);
    s = __fmaf_rn(a[1], W1[1 * HDIM + h], s);
    s = __fmaf_rn(a[2], W1[2 * HDIM + h], s);
    s = __fmaf_rn(a[3], W1[3 * HDIM + h], s);
    s = __fmaf_rn(a[4], W1[4 * HDIM + h], s);
    s = __fmaf_rn(a[5], W1[5 * HDIM + h], s);
    s = __fadd_rn(s, b1[h]);
    h1[gid] = fmaxf(s, 0.f);
}

// ---------------------------------------------------------------------------
// FP32 SGEMM (round-3 proven) — ENCODER ONLY (argmin-critical path)
// ---------------------------------------------------------------------------
template <int RELU>
__global__ __launch_bounds__(256)
void sgemm(const float* __restrict__ Am, const float* __restrict__ Bm,
           const float* __restrict__ bias, float* __restrict__ Cm,
           int M, int Nn, int Kk)
{
    __shared__ float As[8][128];
    __shared__ float Bs[8][128];

    int tid = threadIdx.x;
    int tx = tid & 15;
    int ty = tid >> 4;
    int mb = blockIdx.y * 128;
    int nb = blockIdx.x * 128;

    int arow = tid >> 1;
    int acol = (tid & 1) * 4;
    int brow = tid >> 5;
    int bcol = (tid & 31) * 4;

    const float* Aptr = Am + (mb + arow) * Kk + acol;
    const float* Bptr = Bm + brow * Nn + nb + bcol;

    float acc[8][8];
#pragma unroll
    for (int i = 0; i < 8; i++)
#pragma unroll
        for (int j = 0; j < 8; j++) acc[i][j] = 0.f;

    for (int k0 = 0; k0 < Kk; k0 += 8) {
        float4 av = *(const float4*)Aptr;
        As[acol + 0][arow] = av.x;
        As[acol + 1][arow] = av.y;
        As[acol + 2][arow] = av.z;
        As[acol + 3][arow] = av.w;
        *(float4*)&Bs[brow][bcol] = *(const float4*)Bptr;
        __syncthreads();

#pragma unroll
        for (int kk = 0; kk < 8; kk++) {
            float4 a0 = *(const float4*)&As[kk][ty * 8];
            float4 a1 = *(const float4*)&As[kk][ty * 8 + 4];
            float4 b0 = *(const float4*)&Bs[kk][tx * 8];
            float4 b1 = *(const float4*)&Bs[kk][tx * 8 + 4];
            float av8[8] = {a0.x, a0.y, a0.z, a0.w, a1.x, a1.y, a1.z, a1.w};
            float bv8[8] = {b0.x, b0.y, b0.z, b0.w, b1.x, b1.y, b1.z, b1.w};
#pragma unroll
            for (int i = 0; i < 8; i++)
#pragma unroll
                for (int j = 0; j < 8; j++)
                    acc[i][j] = __fmaf_rn(av8[i], bv8[j], acc[i][j]);
        }
        __syncthreads();
        Aptr += 8;
        Bptr += 8 * Nn;
    }

#pragma unroll
    for (int i = 0; i < 8; i++) {
        int row = mb + ty * 8 + i;
        float* Crow = Cm + row * Nn + nb + tx * 8;
        const float* brow2 = bias + nb + tx * 8;
#pragma unroll
        for (int j = 0; j < 8; j++) {
            float v = __fadd_rn(acc[i][j], brow2[j]);
            if (RELU) v = fmaxf(v, 0.f);
            Crow[j] = v;
        }
    }
}

// ---------------------------------------------------------------------------
// VQ kernel (round-3 proven version, byte-for-byte semantics)
// ---------------------------------------------------------------------------
__global__ __launch_bounds__(256)
void k_vq(const float* __restrict__ lat, const float* __restrict__ cb,
          const float* __restrict__ cn, const float* __restrict__ ln,
          float* __restrict__ out, float* __restrict__ gq,
          float* __restrict__ part)
{
    __shared__ float Ls[DDIM][68];
    __shared__ float Cs[8][68];
    __shared__ int s_ind[64];
    __shared__ float s_red[256];

    int tid = threadIdx.x;
    int tx = tid & 15;
    int ty = tid >> 4;
    int m0 = blockIdx.x * 64;

#pragma unroll
    for (int i = 0; i < 8; i++) {
        int e = tid + i * 256;
        int r = e >> 5;
        int d4 = (e & 31) * 4;
        float4 v = *(const float4*)(lat + (m0 + r) * DDIM + d4);
        Ls[d4 + 0][r] = v.x;
        Ls[d4 + 1][r] = v.y;
        Ls[d4 + 2][r] = v.z;
        Ls[d4 + 3][r] = v.w;
    }
    __syncthreads();

    float Lrow[4];
#pragma unroll
    for (int i = 0; i < 4; i++) Lrow[i] = ln[m0 + ty * 4 + i];

    float bestv[4];
    int besti[4];
#pragma unroll
    for (int i = 0; i < 4; i++) { bestv[i] = 3.4e38f; besti[i] = 0; }

    for (int kt = 0; kt < KCB / 64; kt++) {
        int kc = kt * 64;
        float acc[4][4];
#pragma unroll
        for (int i = 0; i < 4; i++)
#pragma unroll
            for (int j = 0; j < 4; j++) acc[i][j] = 0.f;

        for (int dc = 0; dc < 16; dc++) {
            int d0 = dc * 8;
            if (tid < 128) {
                int code = tid >> 1;
                int dd0 = (tid & 1) * 4;
                float4 v = *(const float4*)(cb + (kc + code) * DDIM + d0 + dd0);
                Cs[dd0 + 0][code] = v.x;
                Cs[dd0 + 1][code] = v.y;
                Cs[dd0 + 2][code] = v.z;
                Cs[dd0 + 3][code] = v.w;
            }
            __syncthreads();
#pragma unroll
            for (int dd = 0; dd < 8; dd++) {
                float4 l = *(const float4*)&Ls[d0 + dd][ty * 4];
                float4 c = *(const float4*)&Cs[dd][tx * 4];
                float lv[4] = {l.x, l.y, l.z, l.w};
                float cv[4] = {c.x, c.y, c.z, c.w};
#pragma unroll
                for (int i = 0; i < 4; i++)
#pragma unroll
                    for (int j = 0; j < 4; j++)
                        acc[i][j] = __fmaf_rn(lv[i], cv[j], acc[i][j]);
            }
            __syncthreads();
        }

#pragma unroll
        for (int j = 0; j < 4; j++) {
            int code = kc + tx * 4 + j;
            float cnv = cn[code];
#pragma unroll
            for (int i = 0; i < 4; i++) {
                float t = __fadd_rn(Lrow[i], cnv);
                float dist = __fsub_rn(t, __fmul_rn(2.f, acc[i][j]));
                if (dist < bestv[i]) { bestv[i] = dist; besti[i] = code; }
            }
        }
    }

#pragma unroll
    for (int i = 0; i < 4; i++) {
        float v = bestv[i];
        int ix = besti[i];
#pragma unroll
        for (int off = 8; off >= 1; off >>= 1) {
            float ov = __shfl_down_sync(0xffffffffu, v, off, 16);
            int oi = __shfl_down_sync(0xffffffffu, ix, off, 16);
            if (ov < v || (ov == v && oi < ix)) { v = ov; ix = oi; }
        }
        if (tx == 0) {
            int mloc = ty * 4 + i;
            s_ind[mloc] = ix;
            out[OUT_INDS + m0 + mloc] = (float)ix;
        }
    }
    __syncthreads();

    float lsum = 0.f;
    for (int e = tid; e < 64 * DDIM; e += 256) {
        int r = e >> 7;
        int d = e & 127;
        float l = Ls[d][r];
        float q = cb[s_ind[r] * DDIM + d];
        float qmL = q - l;
        float qst = l + qmL;
        int m = m0 + r;
        out[OUT_Q + m * DDIM + d] = qst;
        gq[m * DDIM + d] = qst;
        lsum += qmL * qmL;
    }
    s_red[tid] = lsum;
    __syncthreads();
    for (int s = 128; s > 0; s >>= 1) {
        if (tid < s) s_red[tid] += s_red[tid + s];
        __syncthreads();
    }
    if (tid == 0) part[blockIdx.x] = s_red[0];
}

// ---------------------------------------------------------------------------
// Weight transpose: out[c][r] = in[r][c]   (K-major weights for tensor MMA)
// ---------------------------------------------------------------------------
__global__ void k_transpose(const float* __restrict__ in, float* __restrict__ out,
                            int R, int C)
{
    __shared__ float t[32][33];
    int c0 = blockIdx.x * 32, r0 = blockIdx.y * 32;
    int x = threadIdx.x, y0 = threadIdx.y;
#pragma unroll
    for (int dy = 0; dy < 32; dy += 8)
        t[y0 + dy][x] = in[(r0 + y0 + dy) * C + c0 + x];
    __syncthreads();
#pragma unroll
    for (int dy = 0; dy < 32; dy += 8)
        out[(c0 + y0 + dy) * R + r0 + x] = t[x][y0 + dy];
}

// ===========================================================================
// Tensor-core TF32 GEMM via mma.sync.m16n8k8 (sm_80+ PTX, works on sm_103
// non-'a' target). C = relu(A[M,K] @ Bt[N,K]^T + bias). DECODER ONLY.
// CTA tile 128x128, 8 warps (4M x 2N), warp tile 32x64, KC=32 double-buffered.
// ===========================================================================
#define TCG_ST 36                          // smem row stride (floats): 4g+tg -> conflict-free frags
#define TCG_BUF (128 * TCG_ST)             // one buffer, one tensor
#define TCG_SMEM (4 * TCG_BUF * 4)         // 2 tensors x 2 buffers, bytes = 73728

__device__ __forceinline__ uint32_t cvt_tf32(float f)
{
    uint32_t r;
    asm("cvt.rna.tf32.f32 %0, %1;" : "=r"(r) : "f"(f));
    return r;
}

__device__ __forceinline__ void mma_tf32(float* c, const uint32_t* a, const uint32_t* b)
{
    asm("mma.sync.aligned.m16n8k8.row.col.f32.tf32.tf32.f32 "
        "{%0,%1,%2,%3}, {%4,%5,%6,%7}, {%8,%9}, {%0,%1,%2,%3};"
        : "+f"(c[0]), "+f"(c[1]), "+f"(c[2]), "+f"(c[3])
        : "r"(a[0]), "r"(a[1]), "r"(a[2]), "r"(a[3]), "r"(b[0]), "r"(b[1]));
}

template <int RELU>
__global__ __launch_bounds__(256)
void tc_gemm(const float* __restrict__ Am, const float* __restrict__ Bt,
             const float* __restrict__ bias, float* __restrict__ Cm,
             int Nn, int Kk)
{
    extern __shared__ float sm[];
    float* As = sm;                 // [2][128][TCG_ST]
    float* Bs = sm + 2 * TCG_BUF;   // [2][128][TCG_ST]

    int tid = threadIdx.x;
    int lane = tid & 31, warp = tid >> 5;
    int wm = warp & 3, wn = warp >> 2;      // 4 m-warps x 2 n-warps
    int g = lane >> 2, tg = lane & 3;
    int mb = blockIdx.y * 128, nb = blockIdx.x * 128;

    int lr = tid >> 1;              // staging row 0..127
    int lc = (tid & 1) * 16;        // staging col 0 or 16

    const float* Ap = Am + (size_t)(mb + lr) * Kk + lc;
    const float* Bp = Bt + (size_t)(nb + lr) * Kk + lc;

    float acc[2][8][4];
#pragma unroll
    for (int mi = 0; mi < 2; mi++)
#pragma unroll
        for (int ni = 0; ni < 8; ni++)
#pragma unroll
            for (int q = 0; q < 4; q++) acc[mi][ni][q] = 0.f;

    float4 pa[4], pb[4];
    // chunk 0 load + stage into buffer 0
#pragma unroll
    for (int i = 0; i < 4; i++) {
        pa[i] = ((const float4*)Ap)[i];
        pb[i] = ((const float4*)Bp)[i];
    }
#pragma unroll
    for (int i = 0; i < 4; i++) {
        uint4 wa = make_uint4(cvt_tf32(pa[i].x), cvt_tf32(pa[i].y), cvt_tf32(pa[i].z), cvt_tf32(pa[i].w));
        uint4 wb = make_uint4(cvt_tf32(pb[i].x), cvt_tf32(pb[i].y), cvt_tf32(pb[i].z), cvt_tf32(pb[i].w));
        *(uint4*)(As + lr * TCG_ST + lc + i * 4) = wa;
        *(uint4*)(Bs + lr * TCG_ST + lc + i * 4) = wb;
    }
    __syncthreads();

    int NC = Kk >> 5;
    for (int ch = 0; ch < NC; ch++) {
        int buf = ch & 1;
        bool pf = (ch + 1 < NC);
        if (pf) {
            Ap += 32; Bp += 32;
#pragma unroll
            for (int i = 0; i < 4; i++) {
                pa[i] = ((const float4*)Ap)[i];
                pb[i] = ((const float4*)Bp)[i];
            }
        }

        const float* Ab = As + buf * TCG_BUF;
        const float* Bb = Bs + buf * TCG_BUF;
#pragma unroll
        for (int k8 = 0; k8 < 4; k8++) {
            int k0 = k8 * 8;
            uint32_t af[2][4], bf[8][2];
#pragma unroll
            for (int mi = 0; mi < 2; mi++) {
                int r = wm * 32 + mi * 16 + g;
                af[mi][0] = __float_as_uint(Ab[r * TCG_ST + k0 + tg]);
                af[mi][1] = __float_as_uint(Ab[(r + 8) * TCG_ST + k0 + tg]);
                af[mi][2] = __float_as_uint(Ab[r * TCG_ST + k0 + tg + 4]);
                af[mi][3] = __float_as_uint(Ab[(r + 8) * TCG_ST + k0 + tg + 4]);
            }
#pragma unroll
            for (int ni = 0; ni < 8; ni++) {
                int n = wn * 64 + ni * 8 + g;
                bf[ni][0] = __float_as_uint(Bb[n * TCG_ST + k0 + tg]);
                bf[ni][1] = __float_as_uint(Bb[n * TCG_ST + k0 + tg + 4]);
            }
#pragma unroll
            for (int mi = 0; mi < 2; mi++)
#pragma unroll
                for (int ni = 0; ni < 8; ni++)
                    mma_tf32(acc[mi][ni], af[mi], bf[ni]);
        }

        if (pf) {
            float* Ad = As + (1 - buf) * TCG_BUF;
            float* Bd = Bs + (1 - buf) * TCG_BUF;
#pragma unroll
            for (int i = 0; i < 4; i++) {
                uint4 wa = make_uint4(cvt_tf32(pa[i].x), cvt_tf32(pa[i].y), cvt_tf32(pa[i].z), cvt_tf32(pa[i].w));
                uint4 wb = make_uint4(cvt_tf32(pb[i].x), cvt_tf32(pb[i].y), cvt_tf32(pb[i].z), cvt_tf32(pb[i].w));
                *(uint4*)(Ad + lr * TCG_ST + lc + i * 4) = wa;
                *(uint4*)(Bd + lr * TCG_ST + lc + i * 4) = wb;
            }
        }
        __syncthreads();
    }

    // epilogue: bias + relu, write per fragment
#pragma unroll
    for (int mi = 0; mi < 2; mi++) {
        int row = mb + wm * 32 + mi * 16 + g;
#pragma unroll
        for (int ni = 0; ni < 8; ni++) {
            int col = nb + wn * 64 + ni * 8 + tg * 2;
            float b0 = __ldg(bias + col), b1 = __ldg(bias + col + 1);
            float v0 = acc[mi][ni][0] + b0, v1 = acc[mi][ni][1] + b1;
            float v2 = acc[mi][ni][2] + b0, v3 = acc[mi][ni][3] + b1;
            if (RELU) {
                v0 = fmaxf(v0, 0.f); v1 = fmaxf(v1, 0.f);
                v2 = fmaxf(v2, 0.f); v3 = fmaxf(v3, 0.f);
            }
            *(float2*)(Cm + (size_t)row * Nn + col) = make_float2(v0, v1);
            *(float2*)(Cm + (size_t)(row + 8) * Nn + col) = make_float2(v2, v3);
        }
    }
}

// ---------------------------------------------------------------------------
// Decoder layer 3: recons = tanh(d2 @ Wd3 + bd3). Warp per row.
// ---------------------------------------------------------------------------
__global__ void k_dec3(const float* __restrict__ d2, const float* __restrict__ Wd3,
                       const float* __restrict__ bd3, float* __restrict__ out)
{
    int warp = (blockIdx.x * blockDim.x + threadIdx.x) >> 5;
    int lane = threadIdx.x & 31;
    const float* row = d2 + warp * HDIM;
    float a0 = 0.f, a1 = 0.f, a2 = 0.f, a3 = 0.f, a4 = 0.f, a5 = 0.f;
#pragma unroll 4
    for (int k = lane; k < HDIM; k += 32) {
        float v = row[k];
        const float* w = Wd3 + k * ADIM;
        a0 += v * w[0]; a1 += v * w[1]; a2 += v * w[2];
        a3 += v * w[3]; a4 += v * w[4]; a5 += v * w[5];
    }
#pragma unroll
    for (int off = 16; off; off >>= 1) {
        a0 += __shfl_xor_sync(0xffffffffu, a0, off);
        a1 += __shfl_xor_sync(0xffffffffu, a1, off);
        a2 += __shfl_xor_sync(0xffffffffu, a2, off);
        a3 += __shfl_xor_sync(0xffffffffu, a3, off);
        a4 += __shfl_xor_sync(0xffffffffu, a4, off);
        a5 += __shfl_xor_sync(0xffffffffu, a5, off);
    }
    if (lane == 0) {
        float* o = out + OUT_REC + warp * ADIM;
        o[0] = tanhf(a0 + bd3[0]);
        o[1] = tanhf(a1 + bd3[1]);
        o[2] = tanhf(a2 + bd3[2]);
        o[3] = tanhf(a3 + bd3[3]);
        o[4] = tanhf(a4 + bd3[4]);
        o[5] = tanhf(a5 + bd3[5]);
    }
}

// ---------------------------------------------------------------------------
// Final loss reduction
// ---------------------------------------------------------------------------
__global__ void k_loss(const float* __restrict__ part, float* __restrict__ out)
{
    __shared__ float s[256];
    int tid = threadIdx.x;
    s[tid] = part[tid] + part[tid + 256];
    __syncthreads();
    for (int st = 128; st > 0; st >>= 1) {
        if (tid < st) s[tid] += s[tid + st];
        __syncthreads();
    }
    if (tid == 0)
        out[OUT_LOSS] = 1.25f * s[0] / (float)(NTOK * DDIM);
}

// ---------------------------------------------------------------------------
extern "C" void kernel_launch(void* const* d_in, const int* in_sizes, int n_in,
                              void* d_out, int out_size)
{
    const float* action = (const float*)d_in[0];
    const float* W1   = (const float*)d_in[1];
    const float* b1   = (const float*)d_in[2];
    const float* W2   = (const float*)d_in[3];
    const float* b2   = (const float*)d_in[4];
    const float* Wmu  = (const float*)d_in[5];
    const float* bmu  = (const float*)d_in[6];
    const float* cb   = (const float*)d_in[7];
    const float* Wd1  = (const float*)d_in[8];
    const float* bd1  = (const float*)d_in[9];
    const float* Wd2  = (const float*)d_in[10];
    const float* bd2  = (const float*)d_in[11];
    const float* Wd3  = (const float*)d_in[12];
    const float* bd3  = (const float*)d_in[13];
    float* out = (float*)d_out;

    float *p_h1, *p_h2, *p_lat, *p_q, *p_ln, *p_cn, *p_part, *p_wt1, *p_wt2;
    cudaGetSymbolAddress((void**)&p_h1, g_h1);
    cudaGetSymbolAddress((void**)&p_h2, g_h2);
    cudaGetSymbolAddress((void**)&p_lat, g_lat);
    cudaGetSymbolAddress((void**)&p_q, g_q);
    cudaGetSymbolAddress((void**)&p_ln, g_ln);
    cudaGetSymbolAddress((void**)&p_cn, g_cn);
    cudaGetSymbolAddress((void**)&p_part, g_part);
    cudaGetSymbolAddress((void**)&p_wt1, g_wt1);
    cudaGetSymbolAddress((void**)&p_wt2, g_wt2);

    cudaFuncSetAttribute(tc_gemm<1>, cudaFuncAttributeMaxDynamicSharedMemorySize,
                         TCG_SMEM);

    // weight transposes + codebook norms (independent of encoder chain)
    k_transpose<<<dim3(HDIM / 32, DDIM / 32), dim3(32, 8)>>>(Wd1, p_wt1, DDIM, HDIM);
    k_transpose<<<dim3(HDIM / 32, HDIM / 32), dim3(32, 8)>>>(Wd2, p_wt2, HDIM, HDIM);
    k_cnorm<<<KCB / 8, 256>>>(cb, p_cn);

    // encoder (fp32-exact — argmin-critical)
    k_enc1<<<(NTOK * HDIM) / 256, 256>>>(action, W1, b1, p_h1);
    sgemm<1><<<dim3(HDIM / 128, NTOK / 128), 256>>>(p_h1, W2, b2, p_h2, NTOK, HDIM, HDIM);
    sgemm<0><<<dim3(DDIM / 128, NTOK / 128), 256>>>(p_h2, Wmu, bmu, p_lat, NTOK, DDIM, HDIM);
    k_rownorm<<<NTOK / 8, 256>>>(p_lat, p_ln);

    // vector quantization
    k_vq<<<VQ_BLOCKS, 256>>>(p_lat, cb, p_cn, p_ln, out, p_q, p_part);

    // decoder (tensor-core tf32 via mma.sync)
    tc_gemm<1><<<dim3(HDIM / 128, NTOK / 128), 256, TCG_SMEM>>>(p_q, p_wt1, bd1, p_h1, HDIM, DDIM);
    tc_gemm<1><<<dim3(HDIM / 128, NTOK / 128), 256, TCG_SMEM>>>(p_h1, p_wt2, bd2, p_h2, HDIM, HDIM);
    k_dec3<<<NTOK / 8, 256>>>(p_h2, Wd3, bd3, out);

    // scalar loss
    k_loss<<<1, 256>>>(p_part, out);
}

// round 7
// speedup vs baseline: 1.4640x; 1.0904x over previous
#include <cuda_runtime.h>
#include <math.h>
#include <stdint.h>

// Problem dims
#define NTOK 32768
#define ADIM 6
#define HDIM 1024
#define DDIM 128
#define KCB  4096

#define VQ_BLOCKS (NTOK / 64)   // 512

// Output layout (float32, concatenated in reference-return order)
#define OUT_INDS 0
#define OUT_Q    (NTOK)
#define OUT_REC  (NTOK + NTOK * DDIM)
#define OUT_LOSS (NTOK + NTOK * DDIM + NTOK * ADIM)

// -------- scratch (device globals; no runtime allocation) --------
__device__ float g_h1[NTOK * HDIM];
__device__ float g_h2[NTOK * HDIM];
__device__ float g_lat[NTOK * DDIM];
__device__ float g_q[NTOK * DDIM];     // tf32-pre-rounded decoder copy of quantized_st
__device__ float g_ln[NTOK];
__device__ float g_cn[KCB];
__device__ float g_part[VQ_BLOCKS];
__device__ float g_wt1[HDIM * DDIM];   // Wd1^T  tf32-pre-rounded
__device__ float g_wt2[HDIM * HDIM];   // Wd2^T  tf32-pre-rounded

__device__ __forceinline__ uint32_t cvt_tf32(float f)
{
    uint32_t r;
    asm("cvt.rna.tf32.f32 %0, %1;" : "=r"(r) : "f"(f));
    return r;
}
__device__ __forceinline__ float round_tf32(float f)
{
    return __uint_as_float(cvt_tf32(f));
}
__device__ __forceinline__ uint32_t smem_u32(const void* p)
{
    uint32_t a;
    asm("{ .reg .u64 t; cvta.to.shared.u64 t, %1; cvt.u32.u64 %0, t; }"
        : "=r"(a) : "l"(p));
    return a;
}
__device__ __forceinline__ void cp16(uint32_t dst, const void* src)
{
    asm volatile("cp.async.cg.shared.global [%0], [%1], 16;"
                 :: "r"(dst), "l"(src) : "memory");
}

// ---------------------------------------------------------------------------
// XLA-style row sum-of-squares (order-critical for argmin tie replication)
// ---------------------------------------------------------------------------
__device__ __forceinline__ float row_sumsq_128(const float* __restrict__ row, int lane)
{
    float acc = 0.f;
#pragma unroll
    for (int i = 0; i < 4; i++) {
        float v = row[lane + i * 32];
        acc = __fadd_rn(acc, __fmul_rn(v, v));
    }
#pragma unroll
    for (int off = 16; off >= 1; off >>= 1)
        acc = __fadd_rn(acc, __shfl_down_sync(0xffffffffu, acc, off));
    return acc;
}

__global__ void k_cnorm(const float* __restrict__ cb, float* __restrict__ cn)
{
    int w = (blockIdx.x * blockDim.x + threadIdx.x) >> 5;
    int lane = threadIdx.x & 31;
    float s = row_sumsq_128(cb + w * DDIM, lane);
    if (lane == 0) cn[w] = s;
}

__global__ void k_rownorm(const float* __restrict__ lat, float* __restrict__ ln)
{
    int w = (blockIdx.x * blockDim.x + threadIdx.x) >> 5;
    int lane = threadIdx.x & 31;
    float s = row_sumsq_128(lat + w * DDIM, lane);
    if (lane == 0) ln[w] = s;
}

// ---------------------------------------------------------------------------
// Encoder layer 1 (A=6)
// ---------------------------------------------------------------------------
__global__ void k_enc1(const float* __restrict__ act, const float* __restrict__ W1,
                       const float* __restrict__ b1, float* __restrict__ h1)
{
    int gid = blockIdx.x * blockDim.x + threadIdx.x;
    int n = gid >> 10;
    int h = gid & 1023;
    const float* a = act + n * ADIM;
    float s = 0.f;
    s = __fmaf_rn(a[0], W1[0 * HDIM + h], s);
    s = __fmaf_rn(a[1], W1[1 * HDIM + h], s);
    s = __fmaf_rn(a[2], W1[2 * HDIM + h], s);
    s = __fmaf_rn(a[3], W1[3 * HDIM + h], s);
    s = __fmaf_rn(a[4], W1[4 * HDIM + h], s);
    s = __fmaf_rn(a[5], W1[5 * HDIM + h], s);
    s = __fadd_rn(s, b1[h]);
    h1[gid] = fmaxf(s, 0.f);
}

// ---------------------------------------------------------------------------
// FP32 SGEMM (round-3 proven) — ENCODER ONLY (argmin-critical path)
// ---------------------------------------------------------------------------
template <int RELU>
__global__ __launch_bounds__(256)
void sgemm(const float* __restrict__ Am, const float* __restrict__ Bm,
           const float* __restrict__ bias, float* __restrict__ Cm,
           int M, int Nn, int Kk)
{
    __shared__ float As[8][128];
    __shared__ float Bs[8][128];

    int tid = threadIdx.x;
    int tx = tid & 15;
    int ty = tid >> 4;
    int mb = blockIdx.y * 128;
    int nb = blockIdx.x * 128;

    int arow = tid >> 1;
    int acol = (tid & 1) * 4;
    int brow = tid >> 5;
    int bcol = (tid & 31) * 4;

    const float* Aptr = Am + (mb + arow) * Kk + acol;
    const float* Bptr = Bm + brow * Nn + nb + bcol;

    float acc[8][8];
#pragma unroll
    for (int i = 0; i < 8; i++)
#pragma unroll
        for (int j = 0; j < 8; j++) acc[i][j] = 0.f;

    for (int k0 = 0; k0 < Kk; k0 += 8) {
        float4 av = *(const float4*)Aptr;
        As[acol + 0][arow] = av.x;
        As[acol + 1][arow] = av.y;
        As[acol + 2][arow] = av.z;
        As[acol + 3][arow] = av.w;
        *(float4*)&Bs[brow][bcol] = *(const float4*)Bptr;
        __syncthreads();

#pragma unroll
        for (int kk = 0; kk < 8; kk++) {
            float4 a0 = *(const float4*)&As[kk][ty * 8];
            float4 a1 = *(const float4*)&As[kk][ty * 8 + 4];
            float4 b0 = *(const float4*)&Bs[kk][tx * 8];
            float4 b1 = *(const float4*)&Bs[kk][tx * 8 + 4];
            float av8[8] = {a0.x, a0.y, a0.z, a0.w, a1.x, a1.y, a1.z, a1.w};
            float bv8[8] = {b0.x, b0.y, b0.z, b0.w, b1.x, b1.y, b1.z, b1.w};
#pragma unroll
            for (int i = 0; i < 8; i++)
#pragma unroll
                for (int j = 0; j < 8; j++)
                    acc[i][j] = __fmaf_rn(av8[i], bv8[j], acc[i][j]);
        }
        __syncthreads();
        Aptr += 8;
        Bptr += 8 * Nn;
    }

#pragma unroll
    for (int i = 0; i < 8; i++) {
        int row = mb + ty * 8 + i;
        float* Crow = Cm + row * Nn + nb + tx * 8;
        const float* brow2 = bias + nb + tx * 8;
#pragma unroll
        for (int j = 0; j < 8; j++) {
            float v = __fadd_rn(acc[i][j], brow2[j]);
            if (RELU) v = fmaxf(v, 0.f);
            Crow[j] = v;
        }
    }
}

// ---------------------------------------------------------------------------
// VQ kernel (round-3 proven semantics; gq copy is tf32-pre-rounded for decoder)
// ---------------------------------------------------------------------------
__global__ __launch_bounds__(256)
void k_vq(const float* __restrict__ lat, const float* __restrict__ cb,
          const float* __restrict__ cn, const float* __restrict__ ln,
          float* __restrict__ out, float* __restrict__ gq,
          float* __restrict__ part)
{
    __shared__ float Ls[DDIM][68];
    __shared__ float Cs[8][68];
    __shared__ int s_ind[64];
    __shared__ float s_red[256];

    int tid = threadIdx.x;
    int tx = tid & 15;
    int ty = tid >> 4;
    int m0 = blockIdx.x * 64;

#pragma unroll
    for (int i = 0; i < 8; i++) {
        int e = tid + i * 256;
        int r = e >> 5;
        int d4 = (e & 31) * 4;
        float4 v = *(const float4*)(lat + (m0 + r) * DDIM + d4);
        Ls[d4 + 0][r] = v.x;
        Ls[d4 + 1][r] = v.y;
        Ls[d4 + 2][r] = v.z;
        Ls[d4 + 3][r] = v.w;
    }
    __syncthreads();

    float Lrow[4];
#pragma unroll
    for (int i = 0; i < 4; i++) Lrow[i] = ln[m0 + ty * 4 + i];

    float bestv[4];
    int besti[4];
#pragma unroll
    for (int i = 0; i < 4; i++) { bestv[i] = 3.4e38f; besti[i] = 0; }

    for (int kt = 0; kt < KCB / 64; kt++) {
        int kc = kt * 64;
        float acc[4][4];
#pragma unroll
        for (int i = 0; i < 4; i++)
#pragma unroll
            for (int j = 0; j < 4; j++) acc[i][j] = 0.f;

        for (int dc = 0; dc < 16; dc++) {
            int d0 = dc * 8;
            if (tid < 128) {
                int code = tid >> 1;
                int dd0 = (tid & 1) * 4;
                float4 v = *(const float4*)(cb + (kc + code) * DDIM + d0 + dd0);
                Cs[dd0 + 0][code] = v.x;
                Cs[dd0 + 1][code] = v.y;
                Cs[dd0 + 2][code] = v.z;
                Cs[dd0 + 3][code] = v.w;
            }
            __syncthreads();
#pragma unroll
            for (int dd = 0; dd < 8; dd++) {
                float4 l = *(const float4*)&Ls[d0 + dd][ty * 4];
                float4 c = *(const float4*)&Cs[dd][tx * 4];
                float lv[4] = {l.x, l.y, l.z, l.w};
                float cv[4] = {c.x, c.y, c.z, c.w};
#pragma unroll
                for (int i = 0; i < 4; i++)
#pragma unroll
                    for (int j = 0; j < 4; j++)
                        acc[i][j] = __fmaf_rn(lv[i], cv[j], acc[i][j]);
            }
            __syncthreads();
        }

#pragma unroll
        for (int j = 0; j < 4; j++) {
            int code = kc + tx * 4 + j;
            float cnv = cn[code];
#pragma unroll
            for (int i = 0; i < 4; i++) {
                float t = __fadd_rn(Lrow[i], cnv);
                float dist = __fsub_rn(t, __fmul_rn(2.f, acc[i][j]));
                if (dist < bestv[i]) { bestv[i] = dist; besti[i] = code; }
            }
        }
    }

#pragma unroll
    for (int i = 0; i < 4; i++) {
        float v = bestv[i];
        int ix = besti[i];
#pragma unroll
        for (int off = 8; off >= 1; off >>= 1) {
            float ov = __shfl_down_sync(0xffffffffu, v, off, 16);
            int oi = __shfl_down_sync(0xffffffffu, ix, off, 16);
            if (ov < v || (ov == v && oi < ix)) { v = ov; ix = oi; }
        }
        if (tx == 0) {
            int mloc = ty * 4 + i;
            s_ind[mloc] = ix;
            out[OUT_INDS + m0 + mloc] = (float)ix;
        }
    }
    __syncthreads();

    float lsum = 0.f;
    for (int e = tid; e < 64 * DDIM; e += 256) {
        int r = e >> 7;
        int d = e & 127;
        float l = Ls[d][r];
        float q = cb[s_ind[r] * DDIM + d];
        float qmL = q - l;
        float qst = l + qmL;
        int m = m0 + r;
        out[OUT_Q + m * DDIM + d] = qst;
        gq[m * DDIM + d] = round_tf32(qst);   // decoder-only pre-rounded copy
        lsum += qmL * qmL;
    }
    s_red[tid] = lsum;
    __syncthreads();
    for (int s = 128; s > 0; s >>= 1) {
        if (tid < s) s_red[tid] += s_red[tid + s];
        __syncthreads();
    }
    if (tid == 0) part[blockIdx.x] = s_red[0];
}

// ---------------------------------------------------------------------------
// Weight transpose + tf32 pre-round: out[c][r] = tf32(in[r][c])
// ---------------------------------------------------------------------------
__global__ void k_transpose(const float* __restrict__ in, float* __restrict__ out,
                            int R, int C)
{
    __shared__ float t[32][33];
    int c0 = blockIdx.x * 32, r0 = blockIdx.y * 32;
    int x = threadIdx.x, y0 = threadIdx.y;
#pragma unroll
    for (int dy = 0; dy < 32; dy += 8)
        t[y0 + dy][x] = in[(r0 + y0 + dy) * C + c0 + x];
    __syncthreads();
#pragma unroll
    for (int dy = 0; dy < 32; dy += 8)
        out[(c0 + y0 + dy) * R + r0 + x] = round_tf32(t[x][y0 + dy]);
}

// ===========================================================================
// tc_gemm v2: mma.sync.m16n8k8 tf32; operands PRE-ROUNDED in gmem ->
// cp.async.cg staging (no cvt, no prefetch regs), 3-stage circular pipeline.
// C = relu(A[M,K] @ Bt[N,K]^T + bias); optional tf32 rounding of output.
// CTA 128x128, 8 warps (4M x 2N), warp tile 32x64, 32-k chunks.
// ===========================================================================
#define TCG_ST 36
#define TCG_TILE (128 * TCG_ST)                 // floats, one tensor one stage
#define TCG_SMEM (3 * 2 * TCG_TILE * 4)         // 110592 bytes

__device__ __forceinline__ void mma_tf32(float* c, const uint32_t* a, const uint32_t* b)
{
    asm("mma.sync.aligned.m16n8k8.row.col.f32.tf32.tf32.f32 "
        "{%0,%1,%2,%3}, {%4,%5,%6,%7}, {%8,%9}, {%0,%1,%2,%3};"
        : "+f"(c[0]), "+f"(c[1]), "+f"(c[2]), "+f"(c[3])
        : "r"(a[0]), "r"(a[1]), "r"(a[2]), "r"(a[3]), "r"(b[0]), "r"(b[1]));
}

template <int RELU, int CVTOUT>
__global__ __launch_bounds__(256, 2)
void tc_gemm(const float* __restrict__ Am, const float* __restrict__ Bt,
             const float* __restrict__ bias, float* __restrict__ Cm,
             int Nn, int Kk)
{
    extern __shared__ float sm[];
    uint32_t sbase = smem_u32(sm);

    int tid = threadIdx.x;
    int lane = tid & 31, warp = tid >> 5;
    int wm = warp & 3, wn = warp >> 2;
    int g = lane >> 2, tg = lane & 3;
    int mb = blockIdx.y * 128, nb = blockIdx.x * 128;

    int lr = tid >> 1;              // staging row 0..127
    int lc = (tid & 1) * 16;        // k offset 0 or 16 within chunk

    const float* Ap = Am + (size_t)(mb + lr) * Kk + lc;
    const float* Bp = Bt + (size_t)(nb + lr) * Kk + lc;
    uint32_t stg_off = (uint32_t)(lr * TCG_ST + lc) * 4;

    float acc[2][8][4];
#pragma unroll
    for (int mi = 0; mi < 2; mi++)
#pragma unroll
        for (int ni = 0; ni < 8; ni++)
#pragma unroll
            for (int q = 0; q < 4; q++) acc[mi][ni][q] = 0.f;

    int NC = Kk >> 5;

    // prologue: stages 0 and 1 in flight
#pragma unroll
    for (int p = 0; p < 2; p++) {
        uint32_t da = sbase + (uint32_t)(p * 2 * TCG_TILE) * 4 + stg_off;
        uint32_t db = da + (uint32_t)TCG_TILE * 4;
        const float* sa = Ap + p * 32;
        const float* sb = Bp + p * 32;
#pragma unroll
        for (int i = 0; i < 4; i++) {
            cp16(da + i * 16, sa + i * 4);
            cp16(db + i * 16, sb + i * 4);
        }
        asm volatile("cp.async.commit_group;" ::: "memory");
    }

    for (int s = 0; s < NC; s++) {
        asm volatile("cp.async.wait_group 1;" ::: "memory");
        __syncthreads();

        // issue stage s+2 (empty commit keeps group accounting uniform)
        int p2 = s + 2;
        if (p2 < NC) {
            int nbuf = p2 - (p2 / 3) * 3;
            uint32_t da = sbase + (uint32_t)(nbuf * 2 * TCG_TILE) * 4 + stg_off;
            uint32_t db = da + (uint32_t)TCG_TILE * 4;
            const float* sa = Ap + p2 * 32;
            const float* sb = Bp + p2 * 32;
#pragma unroll
            for (int i = 0; i < 4; i++) {
                cp16(da + i * 16, sa + i * 4);
                cp16(db + i * 16, sb + i * 4);
            }
        }
        asm volatile("cp.async.commit_group;" ::: "memory");

        int buf = s - (s / 3) * 3;
        const float* Ab = sm + buf * 2 * TCG_TILE;
        const float* Bb = Ab + TCG_TILE;
#pragma unroll
        for (int k8 = 0; k8 < 4; k8++) {
            int k0 = k8 * 8;
            uint32_t af[2][4], bf[8][2];
#pragma unroll
            for (int mi = 0; mi < 2; mi++) {
                int r = wm * 32 + mi * 16 + g;
                af[mi][0] = __float_as_uint(Ab[r * TCG_ST + k0 + tg]);
                af[mi][1] = __float_as_uint(Ab[(r + 8) * TCG_ST + k0 + tg]);
                af[mi][2] = __float_as_uint(Ab[r * TCG_ST + k0 + tg + 4]);
                af[mi][3] = __float_as_uint(Ab[(r + 8) * TCG_ST + k0 + tg + 4]);
            }
#pragma unroll
            for (int ni = 0; ni < 8; ni++) {
                int n = wn * 64 + ni * 8 + g;
                bf[ni][0] = __float_as_uint(Bb[n * TCG_ST + k0 + tg]);
                bf[ni][1] = __float_as_uint(Bb[n * TCG_ST + k0 + tg + 4]);
            }
#pragma unroll
            for (int mi = 0; mi < 2; mi++)
#pragma unroll
                for (int ni = 0; ni < 8; ni++)
                    mma_tf32(acc[mi][ni], af[mi], bf[ni]);
        }
    }

    // epilogue: bias + relu (+ optional tf32 round for next tc_gemm's A)
#pragma unroll
    for (int mi = 0; mi < 2; mi++) {
        int row = mb + wm * 32 + mi * 16 + g;
#pragma unroll
        for (int ni = 0; ni < 8; ni++) {
            int col = nb + wn * 64 + ni * 8 + tg * 2;
            float b0 = __ldg(bias + col), b1 = __ldg(bias + col + 1);
            float v0 = acc[mi][ni][0] + b0, v1 = acc[mi][ni][1] + b1;
            float v2 = acc[mi][ni][2] + b0, v3 = acc[mi][ni][3] + b1;
            if (RELU) {
                v0 = fmaxf(v0, 0.f); v1 = fmaxf(v1, 0.f);
                v2 = fmaxf(v2, 0.f); v3 = fmaxf(v3, 0.f);
            }
            if (CVTOUT) {
                v0 = round_tf32(v0); v1 = round_tf32(v1);
                v2 = round_tf32(v2); v3 = round_tf32(v3);
            }
            *(float2*)(Cm + (size_t)row * Nn + col) = make_float2(v0, v1);
            *(float2*)(Cm + (size_t)(row + 8) * Nn + col) = make_float2(v2, v3);
        }
    }
}

// ---------------------------------------------------------------------------
// Decoder layer 3: recons = tanh(d2 @ Wd3 + bd3). Warp per row.
// ---------------------------------------------------------------------------
__global__ void k_dec3(const float* __restrict__ d2, const float* __restrict__ Wd3,
                       const float* __restrict__ bd3, float* __restrict__ out)
{
    int warp = (blockIdx.x * blockDim.x + threadIdx.x) >> 5;
    int lane = threadIdx.x & 31;
    const float* row = d2 + warp * HDIM;
    float a0 = 0.f, a1 = 0.f, a2 = 0.f, a3 = 0.f, a4 = 0.f, a5 = 0.f;
#pragma unroll 4
    for (int k = lane; k < HDIM; k += 32) {
        float v = row[k];
        const float* w = Wd3 + k * ADIM;
        a0 += v * w[0]; a1 += v * w[1]; a2 += v * w[2];
        a3 += v * w[3]; a4 += v * w[4]; a5 += v * w[5];
    }
#pragma unroll
    for (int off = 16; off; off >>= 1) {
        a0 += __shfl_xor_sync(0xffffffffu, a0, off);
        a1 += __shfl_xor_sync(0xffffffffu, a1, off);
        a2 += __shfl_xor_sync(0xffffffffu, a2, off);
        a3 += __shfl_xor_sync(0xffffffffu, a3, off);
        a4 += __shfl_xor_sync(0xffffffffu, a4, off);
        a5 += __shfl_xor_sync(0xffffffffu, a5, off);
    }
    if (lane == 0) {
        float* o = out + OUT_REC + warp * ADIM;
        o[0] = tanhf(a0 + bd3[0]);
        o[1] = tanhf(a1 + bd3[1]);
        o[2] = tanhf(a2 + bd3[2]);
        o[3] = tanhf(a3 + bd3[3]);
        o[4] = tanhf(a4 + bd3[4]);
        o[5] = tanhf(a5 + bd3[5]);
    }
}

// ---------------------------------------------------------------------------
// Final loss reduction
// ---------------------------------------------------------------------------
__global__ void k_loss(const float* __restrict__ part, float* __restrict__ out)
{
    __shared__ float s[256];
    int tid = threadIdx.x;
    s[tid] = part[tid] + part[tid + 256];
    __syncthreads();
    for (int st = 128; st > 0; st >>= 1) {
        if (tid < st) s[tid] += s[tid + st];
        __syncthreads();
    }
    if (tid == 0)
        out[OUT_LOSS] = 1.25f * s[0] / (float)(NTOK * DDIM);
}

// ---------------------------------------------------------------------------
extern "C" void kernel_launch(void* const* d_in, const int* in_sizes, int n_in,
                              void* d_out, int out_size)
{
    const float* action = (const float*)d_in[0];
    const float* W1   = (const float*)d_in[1];
    const float* b1   = (const float*)d_in[2];
    const float* W2   = (const float*)d_in[3];
    const float* b2   = (const float*)d_in[4];
    const float* Wmu  = (const float*)d_in[5];
    const float* bmu  = (const float*)d_in[6];
    const float* cb   = (const float*)d_in[7];
    const float* Wd1  = (const float*)d_in[8];
    const float* bd1  = (const float*)d_in[9];
    const float* Wd2  = (const float*)d_in[10];
    const float* bd2  = (const float*)d_in[11];
    const float* Wd3  = (const float*)d_in[12];
    const float* bd3  = (const float*)d_in[13];
    float* out = (float*)d_out;

    float *p_h1, *p_h2, *p_lat, *p_q, *p_ln, *p_cn, *p_part, *p_wt1, *p_wt2;
    cudaGetSymbolAddress((void**)&p_h1, g_h1);
    cudaGetSymbolAddress((void**)&p_h2, g_h2);
    cudaGetSymbolAddress((void**)&p_lat, g_lat);
    cudaGetSymbolAddress((void**)&p_q, g_q);
    cudaGetSymbolAddress((void**)&p_ln, g_ln);
    cudaGetSymbolAddress((void**)&p_cn, g_cn);
    cudaGetSymbolAddress((void**)&p_part, g_part);
    cudaGetSymbolAddress((void**)&p_wt1, g_wt1);
    cudaGetSymbolAddress((void**)&p_wt2, g_wt2);

    cudaFuncSetAttribute(tc_gemm<1, 1>, cudaFuncAttributeMaxDynamicSharedMemorySize,
                         TCG_SMEM);
    cudaFuncSetAttribute(tc_gemm<1, 0>, cudaFuncAttributeMaxDynamicSharedMemorySize,
                         TCG_SMEM);

    // weight transposes (tf32 pre-round) + codebook norms
    k_transpose<<<dim3(HDIM / 32, DDIM / 32), dim3(32, 8)>>>(Wd1, p_wt1, DDIM, HDIM);
    k_transpose<<<dim3(HDIM / 32, HDIM / 32), dim3(32, 8)>>>(Wd2, p_wt2, HDIM, HDIM);
    k_cnorm<<<KCB / 8, 256>>>(cb, p_cn);

    // encoder (fp32-exact — argmin-critical)
    k_enc1<<<(NTOK * HDIM) / 256, 256>>>(action, W1, b1, p_h1);
    sgemm<1><<<dim3(HDIM / 128, NTOK / 128), 256>>>(p_h1, W2, b2, p_h2, NTOK, HDIM, HDIM);
    sgemm<0><<<dim3(DDIM / 128, NTOK / 128), 256>>>(p_h2, Wmu, bmu, p_lat, NTOK, DDIM, HDIM);
    k_rownorm<<<NTOK / 8, 256>>>(p_lat, p_ln);

    // vector quantization
    k_vq<<<VQ_BLOCKS, 256>>>(p_lat, cb, p_cn, p_ln, out, p_q, p_part);

    // decoder (tensor-core tf32, cp.async pipelined)
    tc_gemm<1, 1><<<dim3(HDIM / 128, NTOK / 128), 256, TCG_SMEM>>>(p_q, p_wt1, bd1, p_h1, HDIM, DDIM);
    tc_gemm<1, 0><<<dim3(HDIM / 128, NTOK / 128), 256, TCG_SMEM>>>(p_h1, p_wt2, bd2, p_h2, HDIM, HDIM);
    k_dec3<<<NTOK / 8, 256>>>(p_h2, Wd3, bd3, out);

    // scalar loss
    k_loss<<<1, 256>>>(p_part, out);
}